// round 3
// baseline (speedup 1.0000x reference)
#include <cuda_runtime.h>

#define BATCH 48
#define HH 128
#define WW 128
#define HW 16384

// ---------------- scratch (device globals; no allocation) ----------------
__device__ float g_in0[BATCH * 16 * HW];   // conv1x1(high) output
__device__ float g_v[BATCH * 16 * HW];     // branch conv output (pre-GN "high")
__device__ float g_u[BATCH * 16 * HW];     // conv1x1(low) output (pre-GN "low")
__device__ float g_z[BATCH * 16 * HW];     // ref conv output (pre-GN)
__device__ float g_seg[BATCH * HW];        // seg logits at 128x128
__device__ float g_part_high[BATCH * 32 * 2];
__device__ float g_part_low[BATCH * 16 * 4];
__device__ float g_part_z[BATCH * 32 * 4];
__device__ float g_stats1[BATCH * 6];      // mH, rH, mL0, rL0, mL1, rL1
__device__ float g_stats2[BATCH * 4];      // m0, r0, m1, r1

__device__ __forceinline__ float mish_f(float x) {
    // x * tanh(softplus(x)) = x * (e^2+2e)/(e^2+2e+2), e = exp(x)
    if (x > 20.f) return x;
    float e = __expf(x);
    float n = e * (e + 2.f);
    return x * n / (n + 2.f);
}

// ---------------- K1: in0 = conv1x1(high, Wc0)  (32 -> 16) ----------------
__global__ __launch_bounds__(256) void k1_conv1x1_high(
    const float* __restrict__ high, const float* __restrict__ Wc0) {
    __shared__ float sw[512];
    int t = threadIdx.x;
    for (int i = t; i < 512; i += 256) sw[i] = Wc0[i];
    __syncthreads();
    int b = blockIdx.y;
    int p0 = blockIdx.x * 1024;
    const float* hb = high + (size_t)b * 32 * HW + p0 + t;
    float* ob = g_in0 + (size_t)b * 16 * HW + p0 + t;
    float acc[4][16];
#pragma unroll
    for (int i = 0; i < 4; i++)
#pragma unroll
        for (int o = 0; o < 16; o++) acc[i][o] = 0.f;
    for (int c = 0; c < 32; c++) {
        float x0 = hb[c * HW], x1 = hb[c * HW + 256];
        float x2 = hb[c * HW + 512], x3 = hb[c * HW + 768];
#pragma unroll
        for (int o = 0; o < 16; o++) {
            float w = sw[o * 32 + c];
            acc[0][o] += x0 * w; acc[1][o] += x1 * w;
            acc[2][o] += x2 * w; acc[3][o] += x3 * w;
        }
    }
#pragma unroll
    for (int o = 0; o < 16; o++) {
        ob[o * HW] = acc[0][o]; ob[o * HW + 256] = acc[1][o];
        ob[o * HW + 512] = acc[2][o]; ob[o * HW + 768] = acc[3][o];
    }
}

// ---------------- K2: v = [conv3x3(in0[0:8],Wc1,d1) ; conv3x3(in0[8:16],Wc2,d2)]
// tile 32x16, 128 threads, 4 rows per thread. + GN-high partial sums.
__global__ __launch_bounds__(128) void k2_branch(
    const float* __restrict__ Wc1, const float* __restrict__ Wc2) {
    __shared__ float sx[5760];   // phase1: [8][18][34], phase2: [8][20][36]
    __shared__ float sw[1152];
    __shared__ float red[128];
    int t = threadIdx.x;
    int b = blockIdx.y;
    int tile = blockIdx.x;
    int x0 = (tile & 3) * 32, y0 = (tile >> 2) * 16;
    for (int i = t; i < 576; i += 128) { sw[i] = Wc1[i]; sw[576 + i] = Wc2[i]; }
    int lx = t & 31, ry = t >> 5;
    const float* in0b = g_in0 + (size_t)b * 16 * HW;
    float* vb = g_v + (size_t)b * 16 * HW;
    float ls1 = 0.f, ls2 = 0.f;

    // ---- phase 1: channels 0..7, dilation 1, halo 1 (18 x 34) ----
    for (int i = t; i < 8 * 18 * 34; i += 128) {
        int c = i / 612; int rem = i - c * 612;
        int yy = rem / 34; int xx = rem - yy * 34;
        int gy = y0 - 1 + yy, gx = x0 - 1 + xx;
        float val = 0.f;
        if ((unsigned)gy < 128u && (unsigned)gx < 128u)
            val = in0b[c * HW + gy * WW + gx];
        sx[i] = val;
    }
    __syncthreads();
    {
        float acc[4][8];
#pragma unroll
        for (int r = 0; r < 4; r++)
#pragma unroll
            for (int o = 0; o < 8; o++) acc[r][o] = 0.f;
        for (int ci = 0; ci < 8; ci++) {
#pragma unroll
            for (int k = 0; k < 9; k++) {
                int ky = k / 3, kx = k - ky * 3;
                float wv[8];
#pragma unroll
                for (int o = 0; o < 8; o++) wv[o] = sw[o * 72 + ci * 9 + k];
#pragma unroll
                for (int r = 0; r < 4; r++) {
                    int ly = ry * 4 + r;
                    float xv = sx[ci * 612 + (ly + ky) * 34 + (lx + kx)];
#pragma unroll
                    for (int o = 0; o < 8; o++) acc[r][o] += xv * wv[o];
                }
            }
        }
#pragma unroll
        for (int r = 0; r < 4; r++) {
            int gy = y0 + ry * 4 + r;
#pragma unroll
            for (int o = 0; o < 8; o++) {
                float v = acc[r][o];
                vb[o * HW + gy * WW + x0 + lx] = v;
                ls1 += v; ls2 += v * v;
            }
        }
    }
    __syncthreads();
    // ---- phase 2: channels 8..15, dilation 2, halo 2 (20 x 36) ----
    for (int i = t; i < 8 * 20 * 36; i += 128) {
        int c = i / 720; int rem = i - c * 720;
        int yy = rem / 36; int xx = rem - yy * 36;
        int gy = y0 - 2 + yy, gx = x0 - 2 + xx;
        float val = 0.f;
        if ((unsigned)gy < 128u && (unsigned)gx < 128u)
            val = in0b[(c + 8) * HW + gy * WW + gx];
        sx[i] = val;
    }
    __syncthreads();
    {
        float acc[4][8];
#pragma unroll
        for (int r = 0; r < 4; r++)
#pragma unroll
            for (int o = 0; o < 8; o++) acc[r][o] = 0.f;
        for (int ci = 0; ci < 8; ci++) {
#pragma unroll
            for (int k = 0; k < 9; k++) {
                int ky = k / 3, kx = k - ky * 3;
                float wv[8];
#pragma unroll
                for (int o = 0; o < 8; o++) wv[o] = sw[576 + o * 72 + ci * 9 + k];
#pragma unroll
                for (int r = 0; r < 4; r++) {
                    int ly = ry * 4 + r;
                    float xv = sx[ci * 720 + (ly + 2 * ky) * 36 + (lx + 2 * kx)];
#pragma unroll
                    for (int o = 0; o < 8; o++) acc[r][o] += xv * wv[o];
                }
            }
        }
#pragma unroll
        for (int r = 0; r < 4; r++) {
            int gy = y0 + ry * 4 + r;
#pragma unroll
            for (int o = 0; o < 8; o++) {
                float v = acc[r][o];
                vb[(o + 8) * HW + gy * WW + x0 + lx] = v;
                ls1 += v; ls2 += v * v;
            }
        }
    }
    // ---- deterministic block reduce of (ls1, ls2) ----
    red[t] = ls1; __syncthreads();
    for (int s = 64; s > 0; s >>= 1) { if (t < s) red[t] += red[t + s]; __syncthreads(); }
    if (t == 0) g_part_high[(b * 32 + tile) * 2 + 0] = red[0];
    __syncthreads();
    red[t] = ls2; __syncthreads();
    for (int s = 64; s > 0; s >>= 1) { if (t < s) red[t] += red[t + s]; __syncthreads(); }
    if (t == 0) g_part_high[(b * 32 + tile) * 2 + 1] = red[0];
}

// ---------------- K3: u = conv1x1(low, Wlow) (24 -> 16), + GN-low partials
__global__ __launch_bounds__(256) void k3_low(
    const float* __restrict__ low, const float* __restrict__ Wlow) {
    __shared__ float sw[384];
    __shared__ float red[256];
    int t = threadIdx.x;
    int b = blockIdx.y;
    int p0 = blockIdx.x * 1024;
    for (int i = t; i < 384; i += 256) sw[i] = Wlow[i];
    __syncthreads();
    const float* lb = low + (size_t)b * 24 * HW + p0 + t;
    float* ub = g_u + (size_t)b * 16 * HW + p0 + t;
    float acc[4][16];
#pragma unroll
    for (int i = 0; i < 4; i++)
#pragma unroll
        for (int o = 0; o < 16; o++) acc[i][o] = 0.f;
    for (int c = 0; c < 24; c++) {
        float x0 = lb[c * HW], x1 = lb[c * HW + 256];
        float x2 = lb[c * HW + 512], x3 = lb[c * HW + 768];
#pragma unroll
        for (int o = 0; o < 16; o++) {
            float w = sw[o * 24 + c];
            acc[0][o] += x0 * w; acc[1][o] += x1 * w;
            acc[2][o] += x2 * w; acc[3][o] += x3 * w;
        }
    }
    float sv[4] = {0.f, 0.f, 0.f, 0.f};   // s0,q0,s1,q1
#pragma unroll
    for (int o = 0; o < 16; o++) {
        float v0 = acc[0][o], v1 = acc[1][o], v2 = acc[2][o], v3 = acc[3][o];
        ub[o * HW] = v0; ub[o * HW + 256] = v1;
        ub[o * HW + 512] = v2; ub[o * HW + 768] = v3;
        int g = (o >> 3) * 2;
        sv[g] += v0 + v1 + v2 + v3;
        sv[g + 1] += v0 * v0 + v1 * v1 + v2 * v2 + v3 * v3;
    }
#pragma unroll
    for (int j = 0; j < 4; j++) {
        red[t] = sv[j]; __syncthreads();
        for (int s = 128; s > 0; s >>= 1) { if (t < s) red[t] += red[t + s]; __syncthreads(); }
        if (t == 0) g_part_low[(b * 16 + blockIdx.x) * 4 + j] = red[0];
        __syncthreads();
    }
}

// ---------------- K4: finalize stats for GN-high (1 group) and GN-low (2 groups)
__global__ void k4_stats1() {
    int b = blockIdx.x; int t = threadIdx.x; // 32 threads
    float h1 = g_part_high[(b * 32 + t) * 2 + 0];
    float h2 = g_part_high[(b * 32 + t) * 2 + 1];
    for (int o = 16; o; o >>= 1) {
        h1 += __shfl_xor_sync(0xffffffffu, h1, o);
        h2 += __shfl_xor_sync(0xffffffffu, h2, o);
    }
    float l[4];
#pragma unroll
    for (int j = 0; j < 4; j++) {
        float v = (t < 16) ? g_part_low[(b * 16 + t) * 4 + j] : 0.f;
        for (int o = 16; o; o >>= 1) v += __shfl_xor_sync(0xffffffffu, v, o);
        l[j] = v;
    }
    if (t == 0) {
        float nH = 16.f * HW;
        float mH = h1 / nH;
        g_stats1[b * 6 + 0] = mH;
        g_stats1[b * 6 + 1] = rsqrtf(h2 / nH - mH * mH + 1e-5f);
        float nL = 8.f * HW;
        float m0 = l[0] / nL;
        g_stats1[b * 6 + 2] = m0;
        g_stats1[b * 6 + 3] = rsqrtf(l[1] / nL - m0 * m0 + 1e-5f);
        float m1 = l[2] / nL;
        g_stats1[b * 6 + 4] = m1;
        g_stats1[b * 6 + 5] = rsqrtf(l[3] / nL - m1 * m1 + 1e-5f);
    }
}

// ---------------- K5: r = mish(GN(v)+GN(u)); z = conv3x3(r, Wref); + GN-z partials
__global__ __launch_bounds__(128) void k5_ref(
    const float* __restrict__ Wref,
    const float* __restrict__ gbn, const float* __restrict__ bbn,
    const float* __restrict__ glow, const float* __restrict__ blow) {
    __shared__ float sr[9792];    // [16][18][34]
    __shared__ float sw[2304];    // [16][16][9]
    __shared__ float sa1[16], sa2[16], sa3[16];
    __shared__ float red[128];
    int t = threadIdx.x;
    int b = blockIdx.y;
    int tile = blockIdx.x;
    int x0 = (tile & 3) * 32, y0 = (tile >> 2) * 16;
    for (int i = t; i < 2304; i += 128) sw[i] = Wref[i];
    if (t < 16) {
        int c = t, g = c >> 3;
        float mH = g_stats1[b * 6 + 0], rH = g_stats1[b * 6 + 1];
        float mL = g_stats1[b * 6 + 2 + 2 * g], rL = g_stats1[b * 6 + 3 + 2 * g];
        float a1 = rH * gbn[c], a2 = rL * glow[c];
        sa1[c] = a1; sa2[c] = a2;
        sa3[c] = bbn[c] + blow[c] - mH * a1 - mL * a2;
    }
    __syncthreads();
    const float* vb = g_v + (size_t)b * 16 * HW;
    const float* ub = g_u + (size_t)b * 16 * HW;
    for (int i = t; i < 9792; i += 128) {
        int c = i / 612; int rem = i - c * 612;
        int yy = rem / 34; int xx = rem - yy * 34;
        int gy = y0 - 1 + yy, gx = x0 - 1 + xx;
        float val = 0.f;
        if ((unsigned)gy < 128u && (unsigned)gx < 128u) {
            int off = c * HW + gy * WW + gx;
            val = mish_f(vb[off] * sa1[c] + ub[off] * sa2[c] + sa3[c]);
        }
        sr[i] = val;
    }
    __syncthreads();
    int lx = t & 31, ry = t >> 5;
    float acc[4][16];
#pragma unroll
    for (int r = 0; r < 4; r++)
#pragma unroll
        for (int o = 0; o < 16; o++) acc[r][o] = 0.f;
    for (int ci = 0; ci < 16; ci++) {
#pragma unroll
        for (int k = 0; k < 9; k++) {
            int ky = k / 3, kx = k - ky * 3;
            float wv[16];
#pragma unroll
            for (int o = 0; o < 16; o++) wv[o] = sw[o * 144 + ci * 9 + k];
#pragma unroll
            for (int r = 0; r < 4; r++) {
                float xv = sr[ci * 612 + (ry * 4 + r + ky) * 34 + (lx + kx)];
#pragma unroll
                for (int o = 0; o < 16; o++) acc[r][o] += xv * wv[o];
            }
        }
    }
    float* zb = g_z + (size_t)b * 16 * HW;
    float sv[4] = {0.f, 0.f, 0.f, 0.f};
#pragma unroll
    for (int r = 0; r < 4; r++) {
        int gy = y0 + ry * 4 + r;
#pragma unroll
        for (int o = 0; o < 16; o++) {
            float z = acc[r][o];
            zb[o * HW + gy * WW + x0 + lx] = z;
            int g = (o >> 3) * 2;
            sv[g] += z; sv[g + 1] += z * z;
        }
    }
#pragma unroll
    for (int j = 0; j < 4; j++) {
        red[t] = sv[j]; __syncthreads();
        for (int s = 64; s > 0; s >>= 1) { if (t < s) red[t] += red[t + s]; __syncthreads(); }
        if (t == 0) g_part_z[(b * 32 + tile) * 4 + j] = red[0];
        __syncthreads();
    }
}

// ---------------- K6: finalize GN-z stats (2 groups)
__global__ void k6_stats2() {
    int b = blockIdx.x; int t = threadIdx.x; // 32 threads
    float l[4];
#pragma unroll
    for (int j = 0; j < 4; j++) {
        float v = g_part_z[(b * 32 + t) * 4 + j];
        for (int o = 16; o; o >>= 1) v += __shfl_xor_sync(0xffffffffu, v, o);
        l[j] = v;
    }
    if (t == 0) {
        float n = 8.f * HW;
        float m0 = l[0] / n;
        g_stats2[b * 4 + 0] = m0;
        g_stats2[b * 4 + 1] = rsqrtf(l[1] / n - m0 * m0 + 1e-5f);
        float m1 = l[2] / n;
        g_stats2[b * 4 + 2] = m1;
        g_stats2[b * 4 + 3] = rsqrtf(l[3] / n - m1 * m1 + 1e-5f);
    }
}

// ---------------- K7: seg = conv1x1(mish(GN(z)), Wseg)
__global__ __launch_bounds__(256) void k7_seg(
    const float* __restrict__ gref, const float* __restrict__ bref,
    const float* __restrict__ Wseg) {
    __shared__ float sa[16], sb[16], sws[16];
    int t = threadIdx.x, b = blockIdx.y;
    int p = blockIdx.x * 256 + t;
    if (t < 16) {
        int g = t >> 3;
        float m = g_stats2[b * 4 + 2 * g], r = g_stats2[b * 4 + 1 + 2 * g];
        float a = r * gref[t];
        sa[t] = a; sb[t] = bref[t] - m * a; sws[t] = Wseg[t];
    }
    __syncthreads();
    const float* zb = g_z + (size_t)b * 16 * HW + p;
    float acc = 0.f;
#pragma unroll
    for (int c = 0; c < 16; c++) {
        float zn = zb[c * HW] * sa[c] + sb[c];
        acc += mish_f(zn) * sws[c];
    }
    g_seg[b * HW + p] = acc;
}

// ---------------- K8: bilinear 128->512 (half-pixel centers, clamp) + sigmoid
// 4 consecutive output pixels per thread -> STG.128
__global__ __launch_bounds__(256) void k8_up(float4* __restrict__ out) {
    int idx4 = blockIdx.x * 256 + threadIdx.x;      // 48*512*512/4 = 3145728
    int idx = idx4 * 4;
    int b = idx >> 18;
    int rem = idx & 262143;
    int oy = rem >> 9, ox0 = rem & 511;
    float sy = (oy + 0.5f) * 0.25f - 0.5f;
    sy = fminf(fmaxf(sy, 0.f), 127.f);
    int y0 = (int)sy;
    float fy = sy - y0;
    int y1 = min(y0 + 1, 127);
    const float* s = g_seg + b * HW;
    const float* r0 = s + y0 * 128;
    const float* r1 = s + y1 * 128;
    float4 o4;
    float res[4];
#pragma unroll
    for (int j = 0; j < 4; j++) {
        int ox = ox0 + j;
        float sx = (ox + 0.5f) * 0.25f - 0.5f;
        sx = fminf(fmaxf(sx, 0.f), 127.f);
        int x0 = (int)sx;
        float fx = sx - x0;
        int x1 = min(x0 + 1, 127);
        float top = r0[x0] + (r0[x1] - r0[x0]) * fx;
        float bot = r1[x0] + (r1[x1] - r1[x0]) * fx;
        float v = top + (bot - top) * fy;
        res[j] = 1.f / (1.f + __expf(-v));
    }
    o4.x = res[0]; o4.y = res[1]; o4.z = res[2]; o4.w = res[3];
    out[idx4] = o4;
}

// ---------------- launch ----------------
extern "C" void kernel_launch(void* const* d_in, const int* in_sizes, int n_in,
                              void* d_out, int out_size) {
    (void)in_sizes; (void)n_in; (void)out_size;
    const float* low  = (const float*)d_in[0];
    const float* high = (const float*)d_in[1];
    const float* Wc0  = (const float*)d_in[2];
    const float* Wc1  = (const float*)d_in[3];
    const float* Wc2  = (const float*)d_in[4];
    const float* gbn  = (const float*)d_in[5];
    const float* bbn  = (const float*)d_in[6];
    const float* Wlow = (const float*)d_in[7];
    const float* glow = (const float*)d_in[8];
    const float* blow = (const float*)d_in[9];
    const float* Wref = (const float*)d_in[10];
    const float* gref = (const float*)d_in[11];
    const float* bref = (const float*)d_in[12];
    const float* Wseg = (const float*)d_in[13];
    float* out = (float*)d_out;

    k1_conv1x1_high<<<dim3(16, 48), 256>>>(high, Wc0);
    k2_branch<<<dim3(32, 48), 128>>>(Wc1, Wc2);
    k3_low<<<dim3(16, 48), 256>>>(low, Wlow);
    k4_stats1<<<48, 32>>>();
    k5_ref<<<dim3(32, 48), 128>>>(Wref, gbn, bbn, glow, blow);
    k6_stats2<<<48, 32>>>();
    k7_seg<<<dim3(64, 48), 256>>>(gref, bref, Wseg);
    k8_up<<<12288, 256>>>((float4*)out);
}